// round 2
// baseline (speedup 1.0000x reference)
#include <cuda_runtime.h>
#include <math.h>

#define BATCH 8
#define NPTS  4096
#define KNN   20
#define TOT   (BATCH * NPTS)

// ---------------- scratch (device globals; no allocation allowed) ----------------
__device__ int   g_idx1[TOT * KNN];
__device__ int   g_idx2[TOT * KNN];
__device__ float g_feat[TOT * 192];   // cols [0,64) = x1, cols [64,192) = x2
__device__ float g_y[TOT * 128];
__device__ float g_z[TOT * 128];
__device__ float g_pool[BATCH * 1024];

// ============================ KNN on 2-D input points ============================
// One block per 256 queries of one batch; all 4096 coords in smem.
__global__ void knn1_kernel(const float* __restrict__ data) {
    __shared__ float2 sc[NPTS];                       // 32 KB
    int b = blockIdx.y;
    const float2* dp = (const float2*)(data + (size_t)b * NPTS * 2);
    for (int j = threadIdx.x; j < NPTS; j += blockDim.x) sc[j] = dp[j];
    __syncthreads();

    int q = blockIdx.x * blockDim.x + threadIdx.x;
    float2 qc = sc[q];
    float qd2 = qc.x * qc.x + qc.y * qc.y;

    float bd[KNN]; int bi[KNN];
#pragma unroll
    for (int t = 0; t < KNN; t++) { bd[t] = INFINITY; bi[t] = 0; }
    float worst = INFINITY; int wpos = 0;

    for (int j = 0; j < NPTS; j++) {
        float2 c = sc[j];
        float d2c = c.x * c.x + c.y * c.y;
        float dot = qc.x * c.x + qc.y * c.y;
        float dist = (qd2 + d2c) - 2.0f * dot;        // same formula as reference
        if (dist < worst) {
            bd[wpos] = dist; bi[wpos] = j;
            worst = bd[0]; wpos = 0;
#pragma unroll
            for (int t = 1; t < KNN; t++) if (bd[t] > worst) { worst = bd[t]; wpos = t; }
        }
    }
    int* op = g_idx1 + (size_t)(b * NPTS + q) * KNN;
#pragma unroll
    for (int t = 0; t < KNN; t++) op[t] = bi[t];
}

// ======================= EdgeConv 1: MLP(4->64->64->64), max over k ==============
// Warp per point, lane owns 2 channels, 4 neighbors batched to amortize weight LDS.
__global__ void conv1_kernel(const float* __restrict__ data,
                             const float* __restrict__ w1, const float* __restrict__ b1,
                             const float* __restrict__ w2, const float* __restrict__ b2,
                             const float* __restrict__ w3, const float* __restrict__ b3) {
    __shared__ float sw1[4 * 64], sw2[64 * 64], sw3[64 * 64];
    __shared__ float sb1[64], sb2[64], sb3[64];
    __shared__ float hs[8][4][64];                    // per-warp hidden exchange

    int tid = threadIdx.x;
    sw1[tid] = w1[tid];
    if (tid < 64) { sb1[tid] = b1[tid]; sb2[tid] = b2[tid]; sb3[tid] = b3[tid]; }
    for (int i = tid; i < 4096; i += 256) { sw2[i] = w2[i]; sw3[i] = w3[i]; }
    __syncthreads();

    int warp = tid >> 5, lane = tid & 31;
    int pt = blockIdx.x * 8 + warp;
    int b  = pt >> 12, pl = pt & (NPTS - 1);
    const float* dp = data + (size_t)b * NPTS * 2;
    float xi0 = dp[2 * pl], xi1 = dp[2 * pl + 1];
    int c0 = lane * 2;
    float m0 = -INFINITY, m1 = -INFINITY;
    const int* ip = g_idx1 + (size_t)pt * KNN;

    for (int g = 0; g < KNN / 4; g++) {
        float e[4][4];
#pragma unroll
        for (int nb = 0; nb < 4; nb++) {
            int j = ip[g * 4 + nb];
            float xj0 = dp[2 * j], xj1 = dp[2 * j + 1];
            e[nb][0] = xi0; e[nb][1] = xi1; e[nb][2] = xj0 - xi0; e[nb][3] = xj1 - xi1;
        }
        // ---- layer 1 (4 -> 64, relu)
        float h[4][2];
#pragma unroll
        for (int nb = 0; nb < 4; nb++) { h[nb][0] = sb1[c0]; h[nb][1] = sb1[c0 + 1]; }
#pragma unroll
        for (int k = 0; k < 4; k++) {
            float2 w = *(const float2*)&sw1[k * 64 + c0];
#pragma unroll
            for (int nb = 0; nb < 4; nb++) {
                h[nb][0] = fmaf(e[nb][k], w.x, h[nb][0]);
                h[nb][1] = fmaf(e[nb][k], w.y, h[nb][1]);
            }
        }
        __syncwarp();
#pragma unroll
        for (int nb = 0; nb < 4; nb++) {
            hs[warp][nb][c0]     = fmaxf(h[nb][0], 0.f);
            hs[warp][nb][c0 + 1] = fmaxf(h[nb][1], 0.f);
        }
        __syncwarp();
        // ---- layer 2 (64 -> 64, relu)
#pragma unroll
        for (int nb = 0; nb < 4; nb++) { h[nb][0] = sb2[c0]; h[nb][1] = sb2[c0 + 1]; }
        for (int k = 0; k < 64; k += 4) {
            float hv[4][4];
#pragma unroll
            for (int nb = 0; nb < 4; nb++) {
                float4 t4 = *(const float4*)&hs[warp][nb][k];
                hv[nb][0] = t4.x; hv[nb][1] = t4.y; hv[nb][2] = t4.z; hv[nb][3] = t4.w;
            }
#pragma unroll
            for (int kk = 0; kk < 4; kk++) {
                float2 w = *(const float2*)&sw2[(k + kk) * 64 + c0];
#pragma unroll
                for (int nb = 0; nb < 4; nb++) {
                    h[nb][0] = fmaf(hv[nb][kk], w.x, h[nb][0]);
                    h[nb][1] = fmaf(hv[nb][kk], w.y, h[nb][1]);
                }
            }
        }
        __syncwarp();
#pragma unroll
        for (int nb = 0; nb < 4; nb++) {
            hs[warp][nb][c0]     = fmaxf(h[nb][0], 0.f);
            hs[warp][nb][c0 + 1] = fmaxf(h[nb][1], 0.f);
        }
        __syncwarp();
        // ---- layer 3 (64 -> 64, no relu) + running max
#pragma unroll
        for (int nb = 0; nb < 4; nb++) { h[nb][0] = sb3[c0]; h[nb][1] = sb3[c0 + 1]; }
        for (int k = 0; k < 64; k += 4) {
            float hv[4][4];
#pragma unroll
            for (int nb = 0; nb < 4; nb++) {
                float4 t4 = *(const float4*)&hs[warp][nb][k];
                hv[nb][0] = t4.x; hv[nb][1] = t4.y; hv[nb][2] = t4.z; hv[nb][3] = t4.w;
            }
#pragma unroll
            for (int kk = 0; kk < 4; kk++) {
                float2 w = *(const float2*)&sw3[(k + kk) * 64 + c0];
#pragma unroll
                for (int nb = 0; nb < 4; nb++) {
                    h[nb][0] = fmaf(hv[nb][kk], w.x, h[nb][0]);
                    h[nb][1] = fmaf(hv[nb][kk], w.y, h[nb][1]);
                }
            }
        }
#pragma unroll
        for (int nb = 0; nb < 4; nb++) {
            m0 = fmaxf(m0, h[nb][0]);
            m1 = fmaxf(m1, h[nb][1]);
        }
    }
    float2 r; r.x = m0; r.y = m1;
    *(float2*)&g_feat[(size_t)pt * 192 + c0] = r;
}

// ============================ KNN on 64-D x1 features ============================
// Thread per query (128/block), candidate tiles of 128x64 in smem.
__global__ void knn2_kernel() {
    __shared__ float cf[128][64];                     // 32 KB
    __shared__ float cd2[128];
    int b = blockIdx.y;
    int tid = threadIdx.x;
    int q = blockIdx.x * 128 + tid;
    const float* fb = g_feat + (size_t)b * NPTS * 192;

    float qf[64];
#pragma unroll
    for (int k = 0; k < 64; k += 4) {
        float4 t = *(const float4*)&fb[(size_t)q * 192 + k];
        qf[k] = t.x; qf[k + 1] = t.y; qf[k + 2] = t.z; qf[k + 3] = t.w;
    }
    float qd2 = 0.f;
#pragma unroll
    for (int k = 0; k < 64; k++) qd2 = fmaf(qf[k], qf[k], qd2);

    float bd[KNN]; int bi[KNN];
#pragma unroll
    for (int t = 0; t < KNN; t++) { bd[t] = INFINITY; bi[t] = 0; }
    float worst = INFINITY; int wpos = 0;

    for (int ct = 0; ct < NPTS / 128; ct++) {
        __syncthreads();
        {
            int c = ct * 128 + tid;
            float d2 = 0.f;
#pragma unroll
            for (int k = 0; k < 64; k += 4) {
                float4 t = *(const float4*)&fb[(size_t)c * 192 + k];
                *(float4*)&cf[tid][k] = t;
                d2 = fmaf(t.x, t.x, d2); d2 = fmaf(t.y, t.y, d2);
                d2 = fmaf(t.z, t.z, d2); d2 = fmaf(t.w, t.w, d2);
            }
            cd2[tid] = d2;
        }
        __syncthreads();
        for (int j = 0; j < 128; j++) {
            float d0 = 0.f, d1 = 0.f, d2s = 0.f, d3 = 0.f;   // 4 chains for ILP
#pragma unroll
            for (int k = 0; k < 64; k += 4) {
                float4 t = *(const float4*)&cf[j][k];
                d0 = fmaf(qf[k],     t.x, d0);
                d1 = fmaf(qf[k + 1], t.y, d1);
                d2s = fmaf(qf[k + 2], t.z, d2s);
                d3 = fmaf(qf[k + 3], t.w, d3);
            }
            float dot = (d0 + d1) + (d2s + d3);
            float dist = (qd2 + cd2[j]) - 2.0f * dot;
            if (dist < worst) {
                bd[wpos] = dist; bi[wpos] = ct * 128 + j;
                worst = bd[0]; wpos = 0;
#pragma unroll
                for (int t = 1; t < KNN; t++) if (bd[t] > worst) { worst = bd[t]; wpos = t; }
            }
        }
    }
    int* op = g_idx2 + (size_t)(b * NPTS + q) * KNN;
#pragma unroll
    for (int t = 0; t < KNN; t++) op[t] = bi[t];
}

// ======= EdgeConv 2 decomposition: single linear layer, so max distributes =======
// y[j] = x1[j] . W[64:128],  z[i] = x1[i] . (W[0:64] - W[64:128]) + b
// x2[i] = z[i] + max_{j in knn(i)} y[j]
__global__ void ygemm_kernel(const float* __restrict__ w, const float* __restrict__ bias) {
    int t = blockIdx.x * blockDim.x + threadIdx.x;
    int pt = t >> 5;
    int c = (t & 31) * 4;
    const float* f = g_feat + (size_t)pt * 192;
    float4 ay = make_float4(0.f, 0.f, 0.f, 0.f);
    float4 az = *(const float4*)&bias[c];
    for (int k = 0; k < 64; k++) {
        float xv = f[k];
        float4 wt = *(const float4*)&w[k * 128 + c];
        float4 wb = *(const float4*)&w[(64 + k) * 128 + c];
        ay.x = fmaf(xv, wb.x, ay.x); ay.y = fmaf(xv, wb.y, ay.y);
        ay.z = fmaf(xv, wb.z, ay.z); ay.w = fmaf(xv, wb.w, ay.w);
        az.x = fmaf(xv, wt.x - wb.x, az.x); az.y = fmaf(xv, wt.y - wb.y, az.y);
        az.z = fmaf(xv, wt.z - wb.z, az.z); az.w = fmaf(xv, wt.w - wb.w, az.w);
    }
    *(float4*)&g_y[(size_t)pt * 128 + c] = ay;
    *(float4*)&g_z[(size_t)pt * 128 + c] = az;
}

__global__ void conv2max_kernel() {
    int gw = (blockIdx.x * blockDim.x + threadIdx.x) >> 5;   // warp per point
    int lane = threadIdx.x & 31;
    int pt = gw;
    int base = (pt >> 12) << 12;
    const int* ip = g_idx2 + (size_t)pt * KNN;
    int c = lane * 4;
    float4 m = make_float4(-INFINITY, -INFINITY, -INFINITY, -INFINITY);
    for (int t = 0; t < KNN; t++) {
        int j = base + ip[t];
        float4 v = *(const float4*)&g_y[(size_t)j * 128 + c];
        m.x = fmaxf(m.x, v.x); m.y = fmaxf(m.y, v.y);
        m.z = fmaxf(m.z, v.z); m.w = fmaxf(m.w, v.w);
    }
    float4 z = *(const float4*)&g_z[(size_t)pt * 128 + c];
    float4 r = make_float4(z.x + m.x, z.y + m.y, z.z + m.z, z.w + m.w);
    *(float4*)&g_feat[(size_t)pt * 192 + 64 + c] = r;
}

// ================ lin1 (192 -> 1024) fused with max over 4096 points ==============
// Block owns (batch, 64 output cols); loops over 64-point M-tiles; no atomics.
__global__ void lin1max_kernel(const float* __restrict__ w, const float* __restrict__ bias) {
    __shared__ float As[64][64];
    __shared__ float Bs[64][64];
    __shared__ float red[16][64];
    int b = blockIdx.y;
    int nc = blockIdx.x * 64;
    int tid = threadIdx.x;
    int tx = tid & 15, ty = tid >> 4;
    float runmax[4] = {-INFINITY, -INFINITY, -INFINITY, -INFINITY};
    const float* fb = g_feat + (size_t)b * NPTS * 192;

    for (int mt = 0; mt < NPTS / 64; mt++) {
        float acc[4][4];
#pragma unroll
        for (int r = 0; r < 4; r++)
#pragma unroll
            for (int cc = 0; cc < 4; cc++) acc[r][cc] = 0.f;

        for (int kc = 0; kc < 3; kc++) {
            for (int i = tid; i < 4096; i += 256) {
                int r = i >> 6, k = i & 63;
                As[r][k] = fb[(size_t)(mt * 64 + r) * 192 + kc * 64 + k];
                Bs[r][k] = w[(size_t)(kc * 64 + r) * 1024 + nc + k];
            }
            __syncthreads();
#pragma unroll 4
            for (int kk = 0; kk < 64; kk++) {
                float4 bv = *(const float4*)&Bs[kk][tx * 4];
                float a0 = As[ty * 4 + 0][kk];
                float a1 = As[ty * 4 + 1][kk];
                float a2 = As[ty * 4 + 2][kk];
                float a3 = As[ty * 4 + 3][kk];
                acc[0][0] = fmaf(a0, bv.x, acc[0][0]); acc[0][1] = fmaf(a0, bv.y, acc[0][1]);
                acc[0][2] = fmaf(a0, bv.z, acc[0][2]); acc[0][3] = fmaf(a0, bv.w, acc[0][3]);
                acc[1][0] = fmaf(a1, bv.x, acc[1][0]); acc[1][1] = fmaf(a1, bv.y, acc[1][1]);
                acc[1][2] = fmaf(a1, bv.z, acc[1][2]); acc[1][3] = fmaf(a1, bv.w, acc[1][3]);
                acc[2][0] = fmaf(a2, bv.x, acc[2][0]); acc[2][1] = fmaf(a2, bv.y, acc[2][1]);
                acc[2][2] = fmaf(a2, bv.z, acc[2][2]); acc[2][3] = fmaf(a2, bv.w, acc[2][3]);
                acc[3][0] = fmaf(a3, bv.x, acc[3][0]); acc[3][1] = fmaf(a3, bv.y, acc[3][1]);
                acc[3][2] = fmaf(a3, bv.z, acc[3][2]); acc[3][3] = fmaf(a3, bv.w, acc[3][3]);
            }
            __syncthreads();
        }
#pragma unroll
        for (int r = 0; r < 4; r++)
#pragma unroll
            for (int cc = 0; cc < 4; cc++) runmax[cc] = fmaxf(runmax[cc], acc[r][cc]);
    }
#pragma unroll
    for (int cc = 0; cc < 4; cc++) red[ty][tx * 4 + cc] = runmax[cc];
    __syncthreads();
    if (ty == 0) {
#pragma unroll
        for (int cc = 0; cc < 4; cc++) {
            float m = red[0][tx * 4 + cc];
#pragma unroll
            for (int t = 1; t < 16; t++) m = fmaxf(m, red[t][tx * 4 + cc]);
            g_pool[b * 1024 + nc + tx * 4 + cc] = m + bias[nc + tx * 4 + cc];
        }
    }
}

// =================== tail MLP (1024->512->256->10) + log_softmax ==================
__global__ void mlp_kernel(const float* __restrict__ mw1, const float* __restrict__ mb1,
                           const float* __restrict__ mw2, const float* __restrict__ mb2,
                           const float* __restrict__ mw3, const float* __restrict__ mb3,
                           float* __restrict__ out) {
    __shared__ float s0[1024];
    __shared__ float s1[512];
    __shared__ float s2[256];
    __shared__ float s3[10];
    int b = blockIdx.x;
    int tid = threadIdx.x;
    for (int i = tid; i < 1024; i += 256) s0[i] = g_pool[b * 1024 + i];
    __syncthreads();
#pragma unroll
    for (int oo = 0; oo < 2; oo++) {
        int o = tid + oo * 256;
        float acc = mb1[o];
        for (int k = 0; k < 1024; k++) acc = fmaf(s0[k], mw1[(size_t)k * 512 + o], acc);
        s1[o] = fmaxf(acc, 0.f);
    }
    __syncthreads();
    {
        float acc = mb2[tid];
        for (int k = 0; k < 512; k++) acc = fmaf(s1[k], mw2[(size_t)k * 256 + tid], acc);
        s2[tid] = fmaxf(acc, 0.f);
    }
    __syncthreads();
    if (tid < 10) {
        float acc = mb3[tid];
        for (int k = 0; k < 256; k++) acc = fmaf(s2[k], mw3[k * 10 + tid], acc);
        s3[tid] = acc;
    }
    __syncthreads();
    if (tid == 0) {
        float mx = s3[0];
        for (int t = 1; t < 10; t++) mx = fmaxf(mx, s3[t]);
        float sum = 0.f;
        for (int t = 0; t < 10; t++) sum += expf(s3[t] - mx);
        float lse = mx + logf(sum);
        for (int t = 0; t < 10; t++) out[b * 10 + t] = s3[t] - lse;
    }
}

// ==================================== launch =====================================
extern "C" void kernel_launch(void* const* d_in, const int* in_sizes, int n_in,
                              void* d_out, int out_size) {
    (void)in_sizes; (void)n_in; (void)out_size;
    const float* data   = (const float*)d_in[0];
    const float* c1w1   = (const float*)d_in[1];
    const float* c1b1   = (const float*)d_in[2];
    const float* c1w2   = (const float*)d_in[3];
    const float* c1b2   = (const float*)d_in[4];
    const float* c1w3   = (const float*)d_in[5];
    const float* c1b3   = (const float*)d_in[6];
    const float* c2w1   = (const float*)d_in[7];
    const float* c2b1   = (const float*)d_in[8];
    const float* lin1_w = (const float*)d_in[9];
    const float* lin1_b = (const float*)d_in[10];
    const float* mw1    = (const float*)d_in[11];
    const float* mb1    = (const float*)d_in[12];
    const float* mw2    = (const float*)d_in[13];
    const float* mb2    = (const float*)d_in[14];
    const float* mw3    = (const float*)d_in[15];
    const float* mb3    = (const float*)d_in[16];
    float* out = (float*)d_out;

    knn1_kernel   <<<dim3(NPTS / 256, BATCH), 256>>>(data);
    conv1_kernel  <<<TOT / 8, 256>>>(data, c1w1, c1b1, c1w2, c1b2, c1w3, c1b3);
    knn2_kernel   <<<dim3(NPTS / 128, BATCH), 128>>>();
    ygemm_kernel  <<<TOT * 32 / 256, 256>>>(c2w1, c2b1);
    conv2max_kernel<<<TOT * 32 / 256, 256>>>();
    lin1max_kernel<<<dim3(16, BATCH), 256>>>(lin1_w, lin1_b);
    mlp_kernel    <<<BATCH, 256>>>(mw1, mb1, mw2, mb2, mw3, mb3, out);
}

// round 7
// speedup vs baseline: 1.1205x; 1.1205x over previous
#include <cuda_runtime.h>
#include <math.h>

#define BATCH 8
#define NPTS  4096
#define KNN   20
#define TOT   (BATCH * NPTS)

// ---------------- scratch (device globals; no allocation allowed) ----------------
__device__ int   g_idx1[TOT * KNN];
__device__ int   g_idx2[TOT * KNN];
__device__ float g_feat[TOT * 192];   // cols [0,64) = x1, cols [64,192) = x2
__device__ float g_y[TOT * 128];
__device__ float g_z[TOT * 128];
__device__ float g_pool[BATCH * 1024];

// ======================= packed-key top-k (argmax tree, no local mem) ============
// key = float_bits(max(dist,0)) with low 5 mantissa bits replaced by slot id.
// Quantization error 2^-18 relative — negligible vs fp32 rounding, and the slot
// id makes all keys unique so the argmax is unambiguous.
__device__ __forceinline__ void topk_insert(unsigned (&keys)[KNN], int (&idx)[KNN],
                                            unsigned &wkey, unsigned &wq,
                                            unsigned cq, int j) {
    int slot = (int)(wkey & 31u);
#pragma unroll
    for (int t = 0; t < KNN; t++)
        if (t == slot) { keys[t] = cq | (unsigned)t; idx[t] = j; }
    // explicit 5-level max tree (19 IMNMX, short critical path)
    unsigned a[10];
#pragma unroll
    for (int t = 0; t < 10; t++) a[t] = max(keys[2 * t], keys[2 * t + 1]);
#pragma unroll
    for (int t = 0; t < 5; t++) a[t] = max(a[t], a[t + 5]);
    unsigned b0 = max(a[0], a[1]);
    unsigned b1 = max(a[2], a[3]);
    wkey = max(max(b0, b1), a[4]);
    wq = wkey & 0xFFFFFFE0u;
}

__device__ __forceinline__ unsigned quant_dist(float dist) {
    return __float_as_uint(fmaxf(dist, 0.0f)) & 0xFFFFFFE0u;
}

// ============================ KNN on 2-D input points ============================
__global__ void knn1_kernel(const float* __restrict__ data) {
    __shared__ float2 sc[NPTS];                       // 32 KB
    int b = blockIdx.y;
    const float2* dp = (const float2*)(data + (size_t)b * NPTS * 2);
    for (int j = threadIdx.x; j < NPTS; j += blockDim.x) sc[j] = dp[j];
    __syncthreads();

    int q = blockIdx.x * blockDim.x + threadIdx.x;
    float2 qc = sc[q];
    float qd2 = qc.x * qc.x + qc.y * qc.y;

    unsigned keys[KNN]; int bi[KNN];
#pragma unroll
    for (int t = 0; t < KNN; t++) { keys[t] = 0x7F800000u | (unsigned)t; bi[t] = 0; }
    unsigned wkey = 0x7F800000u | 19u;
    unsigned wq = 0x7F800000u;

    for (int j = 0; j < NPTS; j++) {
        float2 c = sc[j];
        float d2c = c.x * c.x + c.y * c.y;
        float dot = qc.x * c.x + qc.y * c.y;
        float dist = (qd2 + d2c) - 2.0f * dot;        // same formula as reference
        unsigned cq = quant_dist(dist);
        if (cq < wq) topk_insert(keys, bi, wkey, wq, cq, j);
    }
    int* op = g_idx1 + (size_t)(b * NPTS + q) * KNN;
#pragma unroll
    for (int t = 0; t < KNN; t++) op[t] = bi[t];
}

// ======================= EdgeConv 1: MLP(4->64->64->64), max over k ==============
__global__ void conv1_kernel(const float* __restrict__ data,
                             const float* __restrict__ w1, const float* __restrict__ b1,
                             const float* __restrict__ w2, const float* __restrict__ b2,
                             const float* __restrict__ w3, const float* __restrict__ b3) {
    __shared__ float sw1[4 * 64], sw2[64 * 64], sw3[64 * 64];
    __shared__ float sb1[64], sb2[64], sb3[64];
    __shared__ float hs[8][4][64];                    // per-warp hidden exchange

    int tid = threadIdx.x;
    sw1[tid] = w1[tid];
    if (tid < 64) { sb1[tid] = b1[tid]; sb2[tid] = b2[tid]; sb3[tid] = b3[tid]; }
    for (int i = tid; i < 4096; i += 256) { sw2[i] = w2[i]; sw3[i] = w3[i]; }
    __syncthreads();

    int warp = tid >> 5, lane = tid & 31;
    int pt = blockIdx.x * 8 + warp;
    int b  = pt >> 12, pl = pt & (NPTS - 1);
    const float* dp = data + (size_t)b * NPTS * 2;
    float xi0 = dp[2 * pl], xi1 = dp[2 * pl + 1];
    int c0 = lane * 2;
    float m0 = -INFINITY, m1 = -INFINITY;
    const int* ip = g_idx1 + (size_t)pt * KNN;

    for (int g = 0; g < KNN / 4; g++) {
        float e[4][4];
#pragma unroll
        for (int nb = 0; nb < 4; nb++) {
            int j = ip[g * 4 + nb];
            float xj0 = dp[2 * j], xj1 = dp[2 * j + 1];
            e[nb][0] = xi0; e[nb][1] = xi1; e[nb][2] = xj0 - xi0; e[nb][3] = xj1 - xi1;
        }
        // ---- layer 1 (4 -> 64, relu)
        float h[4][2];
#pragma unroll
        for (int nb = 0; nb < 4; nb++) { h[nb][0] = sb1[c0]; h[nb][1] = sb1[c0 + 1]; }
#pragma unroll
        for (int k = 0; k < 4; k++) {
            float2 w = *(const float2*)&sw1[k * 64 + c0];
#pragma unroll
            for (int nb = 0; nb < 4; nb++) {
                h[nb][0] = fmaf(e[nb][k], w.x, h[nb][0]);
                h[nb][1] = fmaf(e[nb][k], w.y, h[nb][1]);
            }
        }
        __syncwarp();
#pragma unroll
        for (int nb = 0; nb < 4; nb++) {
            hs[warp][nb][c0]     = fmaxf(h[nb][0], 0.f);
            hs[warp][nb][c0 + 1] = fmaxf(h[nb][1], 0.f);
        }
        __syncwarp();
        // ---- layer 2 (64 -> 64, relu)
#pragma unroll
        for (int nb = 0; nb < 4; nb++) { h[nb][0] = sb2[c0]; h[nb][1] = sb2[c0 + 1]; }
        for (int k = 0; k < 64; k += 4) {
            float hv[4][4];
#pragma unroll
            for (int nb = 0; nb < 4; nb++) {
                float4 t4 = *(const float4*)&hs[warp][nb][k];
                hv[nb][0] = t4.x; hv[nb][1] = t4.y; hv[nb][2] = t4.z; hv[nb][3] = t4.w;
            }
#pragma unroll
            for (int kk = 0; kk < 4; kk++) {
                float2 w = *(const float2*)&sw2[(k + kk) * 64 + c0];
#pragma unroll
                for (int nb = 0; nb < 4; nb++) {
                    h[nb][0] = fmaf(hv[nb][kk], w.x, h[nb][0]);
                    h[nb][1] = fmaf(hv[nb][kk], w.y, h[nb][1]);
                }
            }
        }
        __syncwarp();
#pragma unroll
        for (int nb = 0; nb < 4; nb++) {
            hs[warp][nb][c0]     = fmaxf(h[nb][0], 0.f);
            hs[warp][nb][c0 + 1] = fmaxf(h[nb][1], 0.f);
        }
        __syncwarp();
        // ---- layer 3 (64 -> 64, no relu) + running max
#pragma unroll
        for (int nb = 0; nb < 4; nb++) { h[nb][0] = sb3[c0]; h[nb][1] = sb3[c0 + 1]; }
        for (int k = 0; k < 64; k += 4) {
            float hv[4][4];
#pragma unroll
            for (int nb = 0; nb < 4; nb++) {
                float4 t4 = *(const float4*)&hs[warp][nb][k];
                hv[nb][0] = t4.x; hv[nb][1] = t4.y; hv[nb][2] = t4.z; hv[nb][3] = t4.w;
            }
#pragma unroll
            for (int kk = 0; kk < 4; kk++) {
                float2 w = *(const float2*)&sw3[(k + kk) * 64 + c0];
#pragma unroll
                for (int nb = 0; nb < 4; nb++) {
                    h[nb][0] = fmaf(hv[nb][kk], w.x, h[nb][0]);
                    h[nb][1] = fmaf(hv[nb][kk], w.y, h[nb][1]);
                }
            }
        }
#pragma unroll
        for (int nb = 0; nb < 4; nb++) {
            m0 = fmaxf(m0, h[nb][0]);
            m1 = fmaxf(m1, h[nb][1]);
        }
    }
    float2 r; r.x = m0; r.y = m1;
    *(float2*)&g_feat[(size_t)pt * 192 + c0] = r;
}

// ============================ KNN on 64-D x1 features ============================
// Thread per query (128/block), candidate tiles of 128x64 in smem (padded rows).
__global__ void knn2_kernel() {
    __shared__ float cf[128][68];                     // padded: conflict-free STS.128
    __shared__ float cd2[128];
    int b = blockIdx.y;
    int tid = threadIdx.x;
    int q = blockIdx.x * 128 + tid;
    const float* fb = g_feat + (size_t)b * NPTS * 192;

    float qf[64];
#pragma unroll
    for (int k = 0; k < 64; k += 4) {
        float4 t = *(const float4*)&fb[(size_t)q * 192 + k];
        qf[k] = t.x; qf[k + 1] = t.y; qf[k + 2] = t.z; qf[k + 3] = t.w;
    }
    float qd2 = 0.f;
#pragma unroll
    for (int k = 0; k < 64; k++) qd2 = fmaf(qf[k], qf[k], qd2);

    unsigned keys[KNN]; int bi[KNN];
#pragma unroll
    for (int t = 0; t < KNN; t++) { keys[t] = 0x7F800000u | (unsigned)t; bi[t] = 0; }
    unsigned wkey = 0x7F800000u | 19u;
    unsigned wq = 0x7F800000u;

    for (int ct = 0; ct < NPTS / 128; ct++) {
        __syncthreads();
        {
            int c = ct * 128 + tid;
            float d2 = 0.f;
#pragma unroll
            for (int k = 0; k < 64; k += 4) {
                float4 t = *(const float4*)&fb[(size_t)c * 192 + k];
                *(float4*)&cf[tid][k] = t;
                d2 = fmaf(t.x, t.x, d2); d2 = fmaf(t.y, t.y, d2);
                d2 = fmaf(t.z, t.z, d2); d2 = fmaf(t.w, t.w, d2);
            }
            cd2[tid] = d2;
        }
        __syncthreads();
        for (int j = 0; j < 128; j++) {
            float d0 = 0.f, d1 = 0.f, d2s = 0.f, d3 = 0.f;   // 4 chains for ILP
#pragma unroll
            for (int k = 0; k < 64; k += 4) {
                float4 t = *(const float4*)&cf[j][k];
                d0 = fmaf(qf[k],     t.x, d0);
                d1 = fmaf(qf[k + 1], t.y, d1);
                d2s = fmaf(qf[k + 2], t.z, d2s);
                d3 = fmaf(qf[k + 3], t.w, d3);
            }
            float dot = (d0 + d1) + (d2s + d3);
            float dist = (qd2 + cd2[j]) - 2.0f * dot;
            unsigned cq = quant_dist(dist);
            if (cq < wq) topk_insert(keys, bi, wkey, wq, cq, ct * 128 + j);
        }
    }
    int* op = g_idx2 + (size_t)(b * NPTS + q) * KNN;
#pragma unroll
    for (int t = 0; t < KNN; t++) op[t] = bi[t];
}

// ======= EdgeConv 2 decomposition: single linear layer, so max distributes =======
// y[j] = x1[j] . W[64:128],  z[i] = x1[i] . (W[0:64] - W[64:128]) + b
// x2[i] = z[i] + max_{j in knn(i)} y[j]
// 8 points per warp: weight L1 traffic amortized 8x; x rows staged in smem.
__global__ void ygemm_kernel(const float* __restrict__ w, const float* __restrict__ bias) {
    __shared__ float sx[8][8 * 64];                   // per-warp x rows (16 KB)
    int tid = threadIdx.x;
    int warp = tid >> 5, lane = tid & 31;
    int p0 = (blockIdx.x * 8 + warp) * 8;             // first of 8 points
    float* sxw = &sx[warp][0];

    // stage 8 x-rows (each 64 floats) cooperatively, coalesced float4
    for (int u = lane; u < 128; u += 32) {            // u = float4 slot
        int row = u >> 4, kk = (u & 15) * 4;
        *(float4*)&sxw[row * 64 + kk] =
            *(const float4*)&g_feat[(size_t)(p0 + row) * 192 + kk];
    }
    __syncwarp();

    int c = lane * 4;
    float4 ay[8], az[8];
    float4 bz = *(const float4*)&bias[c];
#pragma unroll
    for (int i = 0; i < 8; i++) { ay[i] = make_float4(0.f, 0.f, 0.f, 0.f); az[i] = bz; }

    for (int k = 0; k < 64; k++) {
        float4 wt = *(const float4*)&w[k * 128 + c];
        float4 wb = *(const float4*)&w[(64 + k) * 128 + c];
        float4 wd = make_float4(wt.x - wb.x, wt.y - wb.y, wt.z - wb.z, wt.w - wb.w);
#pragma unroll
        for (int i = 0; i < 8; i++) {
            float xv = sxw[i * 64 + k];
            ay[i].x = fmaf(xv, wb.x, ay[i].x); ay[i].y = fmaf(xv, wb.y, ay[i].y);
            ay[i].z = fmaf(xv, wb.z, ay[i].z); ay[i].w = fmaf(xv, wb.w, ay[i].w);
            az[i].x = fmaf(xv, wd.x, az[i].x); az[i].y = fmaf(xv, wd.y, az[i].y);
            az[i].z = fmaf(xv, wd.z, az[i].z); az[i].w = fmaf(xv, wd.w, az[i].w);
        }
    }
#pragma unroll
    for (int i = 0; i < 8; i++) {
        *(float4*)&g_y[(size_t)(p0 + i) * 128 + c] = ay[i];
        *(float4*)&g_z[(size_t)(p0 + i) * 128 + c] = az[i];
    }
}

__global__ void conv2max_kernel() {
    int gw = (blockIdx.x * blockDim.x + threadIdx.x) >> 5;   // warp per point
    int lane = threadIdx.x & 31;
    int pt = gw;
    int base = (pt >> 12) << 12;
    const int* ip = g_idx2 + (size_t)pt * KNN;
    int c = lane * 4;
    float4 m = make_float4(-INFINITY, -INFINITY, -INFINITY, -INFINITY);
    for (int t = 0; t < KNN; t++) {
        int j = base + ip[t];
        float4 v = *(const float4*)&g_y[(size_t)j * 128 + c];
        m.x = fmaxf(m.x, v.x); m.y = fmaxf(m.y, v.y);
        m.z = fmaxf(m.z, v.z); m.w = fmaxf(m.w, v.w);
    }
    float4 z = *(const float4*)&g_z[(size_t)pt * 128 + c];
    float4 r = make_float4(z.x + m.x, z.y + m.y, z.z + m.z, z.w + m.w);
    *(float4*)&g_feat[(size_t)pt * 192 + 64 + c] = r;
}

// ================ lin1 (192 -> 1024) fused with max over 4096 points ==============
// A-tile stored TRANSPOSED (padded) so the per-row reads are conflict-free.
__global__ void lin1max_kernel(const float* __restrict__ w, const float* __restrict__ bias) {
    __shared__ float AsT[64][65];                     // [k][row], pad 65: no STS conflicts
    __shared__ float Bs[64][64];
    __shared__ float red[16][64];
    int b = blockIdx.y;
    int nc = blockIdx.x * 64;
    int tid = threadIdx.x;
    int tx = tid & 15, ty = tid >> 4;
    float runmax[4] = {-INFINITY, -INFINITY, -INFINITY, -INFINITY};
    const float* fb = g_feat + (size_t)b * NPTS * 192;

    for (int mt = 0; mt < NPTS / 64; mt++) {
        float acc[4][4];
#pragma unroll
        for (int r = 0; r < 4; r++)
#pragma unroll
            for (int cc = 0; cc < 4; cc++) acc[r][cc] = 0.f;

        for (int kc = 0; kc < 3; kc++) {
            for (int i = tid; i < 4096; i += 256) {
                int k = i & 63, r = i >> 6;
                // coalesced read (lanes vary k), conflict-free transposed store
                AsT[k][r] = fb[(size_t)(mt * 64 + r) * 192 + kc * 64 + k];
                Bs[r][k]  = w[(size_t)(kc * 64 + r) * 1024 + nc + k];
            }
            __syncthreads();
#pragma unroll 4
            for (int kk = 0; kk < 64; kk++) {
                float4 bv = *(const float4*)&Bs[kk][tx * 4];
                float a0 = AsT[kk][ty * 4 + 0];
                float a1 = AsT[kk][ty * 4 + 1];
                float a2 = AsT[kk][ty * 4 + 2];
                float a3 = AsT[kk][ty * 4 + 3];
                acc[0][0] = fmaf(a0, bv.x, acc[0][0]); acc[0][1] = fmaf(a0, bv.y, acc[0][1]);
                acc[0][2] = fmaf(a0, bv.z, acc[0][2]); acc[0][3] = fmaf(a0, bv.w, acc[0][3]);
                acc[1][0] = fmaf(a1, bv.x, acc[1][0]); acc[1][1] = fmaf(a1, bv.y, acc[1][1]);
                acc[1][2] = fmaf(a1, bv.z, acc[1][2]); acc[1][3] = fmaf(a1, bv.w, acc[1][3]);
                acc[2][0] = fmaf(a2, bv.x, acc[2][0]); acc[2][1] = fmaf(a2, bv.y, acc[2][1]);
                acc[2][2] = fmaf(a2, bv.z, acc[2][2]); acc[2][3] = fmaf(a2, bv.w, acc[2][3]);
                acc[3][0] = fmaf(a3, bv.x, acc[3][0]); acc[3][1] = fmaf(a3, bv.y, acc[3][1]);
                acc[3][2] = fmaf(a3, bv.z, acc[3][2]); acc[3][3] = fmaf(a3, bv.w, acc[3][3]);
            }
            __syncthreads();
        }
#pragma unroll
        for (int r = 0; r < 4; r++)
#pragma unroll
            for (int cc = 0; cc < 4; cc++) runmax[cc] = fmaxf(runmax[cc], acc[r][cc]);
    }
#pragma unroll
    for (int cc = 0; cc < 4; cc++) red[ty][tx * 4 + cc] = runmax[cc];
    __syncthreads();
    if (ty == 0) {
#pragma unroll
        for (int cc = 0; cc < 4; cc++) {
            float m = red[0][tx * 4 + cc];
#pragma unroll
            for (int t = 1; t < 16; t++) m = fmaxf(m, red[t][tx * 4 + cc]);
            g_pool[b * 1024 + nc + tx * 4 + cc] = m + bias[nc + tx * 4 + cc];
        }
    }
}

// =================== tail MLP (1024->512->256->10) + log_softmax ==================
__global__ void mlp_kernel(const float* __restrict__ mw1, const float* __restrict__ mb1,
                           const float* __restrict__ mw2, const float* __restrict__ mb2,
                           const float* __restrict__ mw3, const float* __restrict__ mb3,
                           float* __restrict__ out) {
    __shared__ float s0[1024];
    __shared__ float s1[512];
    __shared__ float s2[256];
    __shared__ float s3[10];
    int b = blockIdx.x;
    int tid = threadIdx.x;
    for (int i = tid; i < 1024; i += 256) s0[i] = g_pool[b * 1024 + i];
    __syncthreads();
#pragma unroll
    for (int oo = 0; oo < 2; oo++) {
        int o = tid + oo * 256;
        float acc = mb1[o];
        for (int k = 0; k < 1024; k++) acc = fmaf(s0[k], mw1[(size_t)k * 512 + o], acc);
        s1[o] = fmaxf(acc, 0.f);
    }
    __syncthreads();
    {
        float acc = mb2[tid];
        for (int k = 0; k < 512; k++) acc = fmaf(s1[k], mw2[(size_t)k * 256 + tid], acc);
        s2[tid] = fmaxf(acc, 0.f);
    }
    __syncthreads();
    if (tid < 10) {
        float acc = mb3[tid];
        for (int k = 0; k < 256; k++) acc = fmaf(s2[k], mw3[k * 10 + tid], acc);
        s3[tid] = acc;
    }
    __syncthreads();
    if (tid == 0) {
        float mx = s3[0];
        for (int t = 1; t < 10; t++) mx = fmaxf(mx, s3[t]);
        float sum = 0.f;
        for (int t = 0; t < 10; t++) sum += expf(s3[t] - mx);
        float lse = mx + logf(sum);
        for (int t = 0; t < 10; t++) out[b * 10 + t] = s3[t] - lse;
    }
}

// ==================================== launch =====================================
extern "C" void kernel_launch(void* const* d_in, const int* in_sizes, int n_in,
                              void* d_out, int out_size) {
    (void)in_sizes; (void)n_in; (void)out_size;
    const float* data   = (const float*)d_in[0];
    const float* c1w1   = (const float*)d_in[1];
    const float* c1b1   = (const float*)d_in[2];
    const float* c1w2   = (const float*)d_in[3];
    const float* c1b2   = (const float*)d_in[4];
    const float* c1w3   = (const float*)d_in[5];
    const float* c1b3   = (const float*)d_in[6];
    const float* c2w1   = (const float*)d_in[7];
    const float* c2b1   = (const float*)d_in[8];
    const float* lin1_w = (const float*)d_in[9];
    const float* lin1_b = (const float*)d_in[10];
    const float* mw1    = (const float*)d_in[11];
    const float* mb1    = (const float*)d_in[12];
    const float* mw2    = (const float*)d_in[13];
    const float* mb2    = (const float*)d_in[14];
    const float* mw3    = (const float*)d_in[15];
    const float* mb3    = (const float*)d_in[16];
    float* out = (float*)d_out;

    knn1_kernel   <<<dim3(NPTS / 256, BATCH), 256>>>(data);
    conv1_kernel  <<<TOT / 8, 256>>>(data, c1w1, c1b1, c1w2, c1b2, c1w3, c1b3);
    knn2_kernel   <<<dim3(NPTS / 128, BATCH), 128>>>();
    ygemm_kernel  <<<TOT / 64, 256>>>(c2w1, c2b1);
    conv2max_kernel<<<TOT * 32 / 256, 256>>>();
    lin1max_kernel<<<dim3(16, BATCH), 256>>>(lin1_w, lin1_b);
    mlp_kernel    <<<BATCH, 256>>>(mw1, mb1, mw2, mb2, mw3, mb3, out);
}